// round 1
// baseline (speedup 1.0000x reference)
#include <cuda_runtime.h>
#include <cuda_bf16.h>

// Problem constants (fixed by the dataset)
#define NN 50000
#define EE 1600000
#define BB 128
#define FX 16
#define FE 4
#define FIN 20
#define MM 64
#define HH 32
#define OO 2048           // M*H
#define ND_STRIDE 60      // 3 basis elems * 20 feats per node

// ---------------- device scratch (static; no allocation allowed) -------------
__device__ __align__(16) float g_rows[NN * FE];
__device__ __align__(16) float g_cols[NN * FE];
__device__ int   g_diag[NN];
__device__ int   g_cnt[BB];
__device__ float g_sumdiag[BB * FIN];
__device__ float g_sumall[BB * FIN];
__device__ float g_g1[BB * FIN];
__device__ float g_g4[BB * FIN];
__device__ float g_factb[BB];
__device__ __align__(16) float g_nd[NN * ND_STRIDE];   // 12 MB
__device__ __align__(16) float g_Wt[100 * OO];         // Wt[k][o], k=e*20+f, o=m*32+h
__device__ __align__(16) float g_Cg[BB * OO];          // per-graph constant + bias
__device__ float g_acc[BB * OO];                        // segment-summed relu output

// ---------------- kernels ----------------------------------------------------

__global__ void k_zero() {
    int i = blockIdx.x * blockDim.x + threadIdx.x;
    int stride = gridDim.x * blockDim.x;
    for (int t = i; t < NN * FE; t += stride) { g_rows[t] = 0.f; g_cols[t] = 0.f; }
    for (int t = i; t < NN; t += stride) g_diag[t] = -1;
    for (int t = i; t < BB; t += stride) g_cnt[t] = 0;
    for (int t = i; t < BB * FIN; t += stride) { g_sumdiag[t] = 0.f; g_sumall[t] = 0.f; }
    for (int t = i; t < BB * OO; t += stride) g_acc[t] = 0.f;
}

__global__ void k_count(const int* __restrict__ batch) {
    int i = blockIdx.x * blockDim.x + threadIdx.x;
    if (i < NN) atomicAdd(&g_cnt[batch[i]], 1);
}

// rearrange kernel_equiv (M,5,H,FIN) -> Wt[k=e*20+f][o=m*32+h]
__global__ void k_prepw(const float* __restrict__ keq) {
    int p = blockIdx.x * blockDim.x + threadIdx.x;
    if (p >= MM * 5 * HH * FIN) return;
    int f = p % FIN;
    int h = (p / FIN) % HH;
    int e = (p / (FIN * HH)) % 5;
    int m = p / (FIN * HH * 5);
    g_Wt[(e * FIN + f) * OO + m * HH + h] = keq[p];
}

__global__ void k_edge(const int* __restrict__ ei, const float* __restrict__ ea) {
    int i = blockIdx.x * blockDim.x + threadIdx.x;
    if (i >= EE) return;
    int s = ei[i];
    int d = ei[EE + i];
    float4 a = reinterpret_cast<const float4*>(ea)[i];
    atomicAdd(&g_rows[s * 4 + 0], a.x);
    atomicAdd(&g_rows[s * 4 + 1], a.y);
    atomicAdd(&g_rows[s * 4 + 2], a.z);
    atomicAdd(&g_rows[s * 4 + 3], a.w);
    atomicAdd(&g_cols[d * 4 + 0], a.x);
    atomicAdd(&g_cols[d * 4 + 1], a.y);
    atomicAdd(&g_cols[d * 4 + 2], a.z);
    atomicAdd(&g_cols[d * 4 + 3], a.w);
    if (s == d) atomicMax(&g_diag[s], i);   // last-update-wins for scatter-set
}

__global__ void k_node(const float* __restrict__ x, const float* __restrict__ ea,
                       const int* __restrict__ batch) {
    int i = blockIdx.x * blockDim.x + threadIdx.x;
    if (i >= NN) return;
    int b = batch[i];
    float fact = 1.f / (float)g_cnt[b];

    const float4* xp = reinterpret_cast<const float4*>(x) + i * 4;
    float4 x0 = xp[0], x1 = xp[1], x2 = xp[2], x3 = xp[3];
    float4 r4 = reinterpret_cast<const float4*>(g_rows)[i];
    float4 c4 = reinterpret_cast<const float4*>(g_cols)[i];
    int did = g_diag[i];
    float4 de = make_float4(0.f, 0.f, 0.f, 0.f);
    if (did >= 0) de = reinterpret_cast<const float4*>(ea)[did];

    float4* nd = reinterpret_cast<float4*>(g_nd + i * ND_STRIDE);
    // basis e0: diag_part = [x, diag_edge]
    nd[0] = x0; nd[1] = x1; nd[2] = x2; nd[3] = x3; nd[4] = de;
    // basis e2: sum_of_rows = [x, rows] * fact
    float4 sx0 = make_float4(x0.x * fact, x0.y * fact, x0.z * fact, x0.w * fact);
    float4 sx1 = make_float4(x1.x * fact, x1.y * fact, x1.z * fact, x1.w * fact);
    float4 sx2 = make_float4(x2.x * fact, x2.y * fact, x2.z * fact, x2.w * fact);
    float4 sx3 = make_float4(x3.x * fact, x3.y * fact, x3.z * fact, x3.w * fact);
    float4 sr = make_float4(r4.x * fact, r4.y * fact, r4.z * fact, r4.w * fact);
    float4 sc = make_float4(c4.x * fact, c4.y * fact, c4.z * fact, c4.w * fact);
    nd[5] = sx0; nd[6] = sx1; nd[7] = sx2; nd[8] = sx3; nd[9] = sr;
    // basis e3: sum_of_cols = [x, cols] * fact
    nd[10] = sx0; nd[11] = sx1; nd[12] = sx2; nd[13] = sx3; nd[14] = sc;

    // per-graph sums
    float dp[FIN]  = { x0.x,x0.y,x0.z,x0.w, x1.x,x1.y,x1.z,x1.w,
                       x2.x,x2.y,x2.z,x2.w, x3.x,x3.y,x3.z,x3.w,
                       de.x,de.y,de.z,de.w };
    float soc[FIN] = { sx0.x,sx0.y,sx0.z,sx0.w, sx1.x,sx1.y,sx1.z,sx1.w,
                       sx2.x,sx2.y,sx2.z,sx2.w, sx3.x,sx3.y,sx3.z,sx3.w,
                       sc.x,sc.y,sc.z,sc.w };
    #pragma unroll
    for (int f = 0; f < FIN; f++) {
        atomicAdd(&g_sumdiag[b * FIN + f], dp[f]);
        atomicAdd(&g_sumall[b * FIN + f], soc[f]);
    }
}

__global__ void k_gfin() {
    int t = blockIdx.x * blockDim.x + threadIdx.x;
    if (t >= BB * FIN) return;
    int b = t / FIN;
    float fact = 1.f / (float)g_cnt[b];
    g_g1[t] = g_sumdiag[t] * fact;            // sum_diag_part
    g_g4[t] = g_sumall[t] * fact * fact;      // sum_all (soc already had one fact)
    if ((t % FIN) == 0) g_factb[b] = fact;
}

// per-graph constant part of repr_eq pre-activation (+ bias_equiv)
__global__ void k_cg(const float* __restrict__ beq) {
    int t = blockIdx.x * blockDim.x + threadIdx.x;
    if (t >= BB * OO) return;
    int b = t / OO;
    int o = t % OO;
    float s = beq[o];
    #pragma unroll
    for (int f = 0; f < FIN; f++) s += g_g1[b * FIN + f] * g_Wt[(1 * FIN + f) * OO + o];
    #pragma unroll
    for (int f = 0; f < FIN; f++) s += g_g4[b * FIN + f] * g_Wt[(4 * FIN + f) * OO + o];
    g_Cg[t] = s;
}

// main fused GEMM: C[n,o] = nd[n,:60] @ Wt'[:60,o] + Cg[g(n),o]; relu; segment-sum
__global__ __launch_bounds__(256) void k_gemm(const int* __restrict__ batch) {
    __shared__ float As[64 * 20];
    __shared__ float Bs[20 * 256];
    __shared__ int   gs[64];
    __shared__ float red[8 * 264];   // [tr][j*33+tc], padded

    int tid = threadIdx.x;
    int tc = tid & 31;
    int tr = tid >> 5;
    int nbase = blockIdx.x * 64;
    int obase = blockIdx.y * 256;

    if (tid < 64) {
        int n = nbase + tid;
        gs[tid] = (n < NN) ? batch[n] : -1;
    }

    float acc[8][8];
    #pragma unroll
    for (int i = 0; i < 8; i++)
        #pragma unroll
        for (int j = 0; j < 8; j++) acc[i][j] = 0.f;

    // three node-basis tiles: nd slot t -> Wt k-offset {0 (e0), 40 (e2), 60 (e3)}
    for (int t = 0; t < 3; t++) {
        int koff = (t == 0) ? 0 : (t == 1 ? 40 : 60);
        for (int p = tid; p < 64 * 20; p += 256) {
            int r = p / 20, f = p % 20;
            int n = nbase + r;
            As[p] = (n < NN) ? g_nd[n * ND_STRIDE + t * 20 + f] : 0.f;
        }
        for (int p = tid; p < 20 * 256; p += 256) {
            int f = p >> 8;           // p / 256
            int c = p & 255;
            Bs[p] = g_Wt[(koff + f) * OO + obase + c];
        }
        __syncthreads();
        #pragma unroll 4
        for (int f = 0; f < 20; f++) {
            float bv[8], av[8];
            #pragma unroll
            for (int j = 0; j < 8; j++) bv[j] = Bs[f * 256 + tc + 32 * j];
            #pragma unroll
            for (int i = 0; i < 8; i++) av[i] = As[(tr + 8 * i) * 20 + f];
            #pragma unroll
            for (int i = 0; i < 8; i++)
                #pragma unroll
                for (int j = 0; j < 8; j++) acc[i][j] = fmaf(av[i], bv[j], acc[i][j]);
        }
        __syncthreads();
    }

    // epilogue: +Cg, relu, segment-reduce (<=2 graphs per 64-node tile)
    int nvalid = NN - nbase; if (nvalid > 64) nvalid = 64;
    int glo = gs[0];
    int ghi = gs[nvalid - 1];
    int npass = (ghi == glo) ? 1 : 2;

    for (int sp = 0; sp < npass; sp++) {
        int gt = sp ? ghi : glo;
        float cg[8];
        #pragma unroll
        for (int j = 0; j < 8; j++) cg[j] = g_Cg[gt * OO + obase + tc + 32 * j];
        float pj[8];
        #pragma unroll
        for (int j = 0; j < 8; j++) pj[j] = 0.f;
        #pragma unroll
        for (int i = 0; i < 8; i++) {
            if (gs[tr + 8 * i] == gt) {
                #pragma unroll
                for (int j = 0; j < 8; j++)
                    pj[j] += fmaxf(acc[i][j] + cg[j], 0.f);
            }
        }
        #pragma unroll
        for (int j = 0; j < 8; j++) red[tr * 264 + j * 33 + tc] = pj[j];
        __syncthreads();
        // cross-tr reduction: thread tid handles (j2 = tid>>5, t2 = tid&31)
        {
            int j2 = tid >> 5, t2 = tid & 31;
            float s = 0.f;
            #pragma unroll
            for (int r8 = 0; r8 < 8; r8++) s += red[r8 * 264 + j2 * 33 + t2];
            atomicAdd(&g_acc[gt * OO + obase + j2 * 32 + t2], s);
        }
        __syncthreads();
    }
}

// out[b,m] = fact_b * sum_h acc[b,m,h]*kinv[m,h]  -  sum_h relu(beq[m,h])*kinv[m,h]
__global__ void k_out(const float* __restrict__ kinv, const float* __restrict__ beq,
                      float* __restrict__ out) {
    int t = blockIdx.x * blockDim.x + threadIdx.x;
    if (t >= BB * MM) return;
    int b = t >> 6;
    int m = t & 63;
    float fb = g_factb[b];
    float s = 0.f, z = 0.f;
    #pragma unroll
    for (int h = 0; h < HH; h++) {
        float kv = kinv[m * HH + h];
        s += g_acc[b * OO + m * HH + h] * kv;
        z += fmaxf(beq[m * HH + h], 0.f) * kv;
    }
    out[t] = fb * s - z;
}

// ---------------- launch ------------------------------------------------------

extern "C" void kernel_launch(void* const* d_in, const int* in_sizes, int n_in,
                              void* d_out, int out_size) {
    const float* x    = (const float*)d_in[0];   // (N,16)
    const float* ea   = (const float*)d_in[1];   // (E,4)
    const float* keq  = (const float*)d_in[2];   // (M,5,H,FIN)
    const float* kinv = (const float*)d_in[3];   // (M,1,1,H)
    const float* beq  = (const float*)d_in[4];   // (1,M,1,H)
    // d_in[5] = bias_inv (cancels in psi - zerograph)
    const int* ei     = (const int*)d_in[6];     // (2,E)
    const int* batch  = (const int*)d_in[7];     // (N,)
    float* out = (float*)d_out;

    k_zero<<<512, 256>>>();
    k_count<<<(NN + 255) / 256, 256>>>(batch);
    k_prepw<<<(MM * 5 * HH * FIN + 255) / 256, 256>>>(keq);
    k_edge<<<(EE + 255) / 256, 256>>>(ei, ea);
    k_node<<<(NN + 255) / 256, 256>>>(x, ea, batch);
    k_gfin<<<(BB * FIN + 255) / 256, 256>>>();
    k_cg<<<(BB * OO) / 256, 256>>>(beq);
    dim3 gg((NN + 63) / 64, OO / 256);
    k_gemm<<<gg, 256>>>(batch);
    k_out<<<(BB * MM + 255) / 256, 256>>>(kinv, beq, out);
}

// round 4
// speedup vs baseline: 1.4039x; 1.4039x over previous
#include <cuda_runtime.h>
#include <cuda_bf16.h>

// Problem constants (fixed by the dataset)
#define NN 50000
#define EE 1600000
#define BB 128
#define FX 16
#define FE 4
#define FIN 20
#define MM 64
#define HH 32
#define OO 2048           // M*H
#define KT 44             // reduced contraction dim: 20(e0) + 16(x,e2+e3) + 4(rows) + 4(cols)

// ---------------- device scratch (static; no allocation allowed) -------------
__device__ __align__(16) float g_rows[NN * FE];
__device__ __align__(16) float g_cols[NN * FE];
__device__ int   g_diag[NN];
__device__ int   g_cnt[BB];
__device__ float g_sumdiag[BB * FIN];
__device__ float g_sumall[BB * FIN];
__device__ float g_g1[BB * FIN];
__device__ float g_g4[BB * FIN];
__device__ float g_factb[BB];
__device__ __align__(16) float g_nd2[NN * KT];         // 8.8 MB, 176B rows (16B aligned)
__device__ __align__(16) float g_W2[KT * OO];          // folded equivariant weights
__device__ __align__(16) float g_W14[40 * OO];         // e1 / e4 weights (for Cg)
__device__ __align__(16) float g_Cg[BB * OO];          // per-graph constant + bias
__device__ float g_acc[BB * OO];                       // segment-summed relu output

// ---------------- kernels ----------------------------------------------------

__global__ void k_zero() {
    int i = blockIdx.x * blockDim.x + threadIdx.x;
    int stride = gridDim.x * blockDim.x;
    for (int t = i; t < NN * FE; t += stride) { g_rows[t] = 0.f; g_cols[t] = 0.f; }
    for (int t = i; t < NN; t += stride) g_diag[t] = -1;
    for (int t = i; t < BB; t += stride) g_cnt[t] = 0;
    for (int t = i; t < BB * FIN; t += stride) { g_sumdiag[t] = 0.f; g_sumall[t] = 0.f; }
    for (int t = i; t < BB * OO; t += stride) g_acc[t] = 0.f;
}

__global__ void k_count(const int* __restrict__ batch) {
    int i = blockIdx.x * blockDim.x + threadIdx.x;
    if (i < NN) atomicAdd(&g_cnt[batch[i]], 1);
}

// fold kernel_equiv (M,5,H,FIN) into g_W2[k][o] (k=0..43) and g_W14[k][o] (k=0..39)
__global__ void k_prepw(const float* __restrict__ keq) {
    int p = blockIdx.x * blockDim.x + threadIdx.x;
    if (p >= 84 * OO) return;
    int o = p & (OO - 1);
    int k = p >> 11;
    int m = o >> 5;
    int h = o & 31;
    const float* base = keq + (m * 5) * HH * FIN + h * FIN;   // [e][f] at stride HH*FIN per e
    float v;
    if (k < 20) {                      // e0, f=k
        v = base[0 * HH * FIN + k];
        g_W2[k * OO + o] = v;
    } else if (k < 36) {               // x-part shared by e2+e3, f=k-20
        int f = k - 20;
        v = base[2 * HH * FIN + f] + base[3 * HH * FIN + f];
        g_W2[k * OO + o] = v;
    } else if (k < 40) {               // rows part: e2, f=16+(k-36)
        v = base[2 * HH * FIN + 16 + (k - 36)];
        g_W2[k * OO + o] = v;
    } else if (k < 44) {               // cols part: e3, f=16+(k-40)
        v = base[3 * HH * FIN + 16 + (k - 40)];
        g_W2[k * OO + o] = v;
    } else if (k < 64) {               // e1, f=k-44
        v = base[1 * HH * FIN + (k - 44)];
        g_W14[(k - 44) * OO + o] = v;
    } else {                           // e4, f=k-64
        v = base[4 * HH * FIN + (k - 64)];
        g_W14[(k - 44) * OO + o] = v;
    }
}

__global__ void k_edge(const int* __restrict__ ei, const float* __restrict__ ea) {
    int i = blockIdx.x * blockDim.x + threadIdx.x;
    if (i >= EE) return;
    int s = ei[i];
    int d = ei[EE + i];
    float4 a = reinterpret_cast<const float4*>(ea)[i];
    atomicAdd(&g_rows[s * 4 + 0], a.x);
    atomicAdd(&g_rows[s * 4 + 1], a.y);
    atomicAdd(&g_rows[s * 4 + 2], a.z);
    atomicAdd(&g_rows[s * 4 + 3], a.w);
    atomicAdd(&g_cols[d * 4 + 0], a.x);
    atomicAdd(&g_cols[d * 4 + 1], a.y);
    atomicAdd(&g_cols[d * 4 + 2], a.z);
    atomicAdd(&g_cols[d * 4 + 3], a.w);
    if (s == d) atomicMax(&g_diag[s], i);   // last-update-wins for scatter-set
}

__global__ void k_node(const float* __restrict__ x, const float* __restrict__ ea,
                       const int* __restrict__ batch) {
    int i = blockIdx.x * blockDim.x + threadIdx.x;
    if (i >= NN) return;
    int b = batch[i];
    float fact = 1.f / (float)g_cnt[b];

    const float4* xp = reinterpret_cast<const float4*>(x) + i * 4;
    float4 x0 = xp[0], x1 = xp[1], x2 = xp[2], x3 = xp[3];
    float4 r4 = reinterpret_cast<const float4*>(g_rows)[i];
    float4 c4 = reinterpret_cast<const float4*>(g_cols)[i];
    int did = g_diag[i];
    float4 de = make_float4(0.f, 0.f, 0.f, 0.f);
    if (did >= 0) de = reinterpret_cast<const float4*>(ea)[did];

    float4 sx0 = make_float4(x0.x * fact, x0.y * fact, x0.z * fact, x0.w * fact);
    float4 sx1 = make_float4(x1.x * fact, x1.y * fact, x1.z * fact, x1.w * fact);
    float4 sx2 = make_float4(x2.x * fact, x2.y * fact, x2.z * fact, x2.w * fact);
    float4 sx3 = make_float4(x3.x * fact, x3.y * fact, x3.z * fact, x3.w * fact);
    float4 sr = make_float4(r4.x * fact, r4.y * fact, r4.z * fact, r4.w * fact);
    float4 sc = make_float4(c4.x * fact, c4.y * fact, c4.z * fact, c4.w * fact);

    float4* nd = reinterpret_cast<float4*>(g_nd2 + i * KT);
    nd[0] = x0; nd[1] = x1; nd[2] = x2; nd[3] = x3;   // diag x
    nd[4] = de;                                       // diag edge
    nd[5] = sx0; nd[6] = sx1; nd[7] = sx2; nd[8] = sx3; // x*fact (shared e2+e3)
    nd[9] = sr;                                       // rows*fact
    nd[10] = sc;                                      // cols*fact

    // per-graph sums
    float dp[FIN]  = { x0.x,x0.y,x0.z,x0.w, x1.x,x1.y,x1.z,x1.w,
                       x2.x,x2.y,x2.z,x2.w, x3.x,x3.y,x3.z,x3.w,
                       de.x,de.y,de.z,de.w };
    float soc[FIN] = { sx0.x,sx0.y,sx0.z,sx0.w, sx1.x,sx1.y,sx1.z,sx1.w,
                       sx2.x,sx2.y,sx2.z,sx2.w, sx3.x,sx3.y,sx3.z,sx3.w,
                       sc.x,sc.y,sc.z,sc.w };
    #pragma unroll
    for (int f = 0; f < FIN; f++) {
        atomicAdd(&g_sumdiag[b * FIN + f], dp[f]);
        atomicAdd(&g_sumall[b * FIN + f], soc[f]);
    }
}

__global__ void k_gfin() {
    int t = blockIdx.x * blockDim.x + threadIdx.x;
    if (t >= BB * FIN) return;
    int b = t / FIN;
    float fact = 1.f / (float)g_cnt[b];
    g_g1[t] = g_sumdiag[t] * fact;            // sum_diag_part
    g_g4[t] = g_sumall[t] * fact * fact;      // sum_all
    if ((t % FIN) == 0) g_factb[b] = fact;
}

// per-graph constant part of repr_eq pre-activation (+ bias_equiv)
__global__ void k_cg(const float* __restrict__ beq) {
    int t = blockIdx.x * blockDim.x + threadIdx.x;
    if (t >= BB * OO) return;
    int b = t / OO;
    int o = t % OO;
    float s = beq[o];
    #pragma unroll
    for (int f = 0; f < FIN; f++) s += g_g1[b * FIN + f] * g_W14[f * OO + o];
    #pragma unroll
    for (int f = 0; f < FIN; f++) s += g_g4[b * FIN + f] * g_W14[(20 + f) * OO + o];
    g_Cg[t] = s;
}

// main fused GEMM: C[n,o] = nd2[n,:44] @ W2[:44,o]; then +Cg[g(n),o], relu, segment-sum.
// tile: 64 rows x 128 cols, 128 threads, 8x8 per thread, float4 smem reads.
__global__ __launch_bounds__(128) void k_gemm(const int* __restrict__ batch) {
    __shared__ float As[KT * 64];      // [f][r]
    __shared__ float Bs[KT * 128];     // [f][c]
    __shared__ int   gs[64];
    __shared__ float red[8 * 128];

    int tid = threadIdx.x;
    int tc = tid & 15;                 // col group (8 cols each)
    int tr = tid >> 4;                 // row group (8 rows each)
    int nbase = blockIdx.x * 64;
    int obase = blockIdx.y * 128;
    int nvalid = NN - nbase; if (nvalid > 64) nvalid = 64;

    if (tid < 64)
        gs[tid] = (tid < nvalid) ? batch[nbase + tid] : -1;

    // load A tile transposed (vectorized global reads, 11 float4 per row)
    for (int p = tid; p < 64 * 11; p += 128) {
        int r = p / 11, q = p % 11;
        float4 v = make_float4(0.f, 0.f, 0.f, 0.f);
        if (r < nvalid)
            v = *reinterpret_cast<const float4*>(&g_nd2[(nbase + r) * KT + q * 4]);
        As[(4 * q + 0) * 64 + r] = v.x;
        As[(4 * q + 1) * 64 + r] = v.y;
        As[(4 * q + 2) * 64 + r] = v.z;
        As[(4 * q + 3) * 64 + r] = v.w;
    }
    // load B tile (vectorized)
    for (int p = tid; p < KT * 32; p += 128) {
        int f = p >> 5, c4 = p & 31;
        *reinterpret_cast<float4*>(&Bs[f * 128 + c4 * 4]) =
            *reinterpret_cast<const float4*>(&g_W2[f * OO + obase + c4 * 4]);
    }
    __syncthreads();

    float acc[8][8];
    #pragma unroll
    for (int i = 0; i < 8; i++)
        #pragma unroll
        for (int j = 0; j < 8; j++) acc[i][j] = 0.f;

    #pragma unroll 4
    for (int f = 0; f < KT; f++) {
        float4 a0 = *reinterpret_cast<const float4*>(&As[f * 64 + tr * 8]);
        float4 a1 = *reinterpret_cast<const float4*>(&As[f * 64 + tr * 8 + 4]);
        float4 b0 = *reinterpret_cast<const float4*>(&Bs[f * 128 + tc * 8]);
        float4 b1 = *reinterpret_cast<const float4*>(&Bs[f * 128 + tc * 8 + 4]);
        float av[8] = { a0.x, a0.y, a0.z, a0.w, a1.x, a1.y, a1.z, a1.w };
        float bv[8] = { b0.x, b0.y, b0.z, b0.w, b1.x, b1.y, b1.z, b1.w };
        #pragma unroll
        for (int i = 0; i < 8; i++)
            #pragma unroll
            for (int j = 0; j < 8; j++)
                acc[i][j] = fmaf(av[i], bv[j], acc[i][j]);
    }

    // epilogue: +Cg, relu, segment-reduce (<=2 graphs per 64-node tile since
    // nodes/graph ~390 > 64)
    int glo = gs[0];
    int ghi = gs[nvalid - 1];
    int npass = (ghi == glo) ? 1 : 2;

    for (int sp = 0; sp < npass; sp++) {
        int gt = sp ? ghi : glo;
        float4 c0 = *reinterpret_cast<const float4*>(&g_Cg[gt * OO + obase + tc * 8]);
        float4 c1 = *reinterpret_cast<const float4*>(&g_Cg[gt * OO + obase + tc * 8 + 4]);
        float cg[8] = { c0.x, c0.y, c0.z, c0.w, c1.x, c1.y, c1.z, c1.w };
        float pj[8];
        #pragma unroll
        for (int j = 0; j < 8; j++) pj[j] = 0.f;
        #pragma unroll
        for (int i = 0; i < 8; i++) {
            if (gs[tr * 8 + i] == gt) {
                #pragma unroll
                for (int j = 0; j < 8; j++)
                    pj[j] += fmaxf(acc[i][j] + cg[j], 0.f);
            }
        }
        __syncthreads();   // red reuse safety across passes
        *reinterpret_cast<float4*>(&red[tr * 128 + tc * 8]) =
            make_float4(pj[0], pj[1], pj[2], pj[3]);
        *reinterpret_cast<float4*>(&red[tr * 128 + tc * 8 + 4]) =
            make_float4(pj[4], pj[5], pj[6], pj[7]);
        __syncthreads();
        float s = 0.f;
        #pragma unroll
        for (int r8 = 0; r8 < 8; r8++) s += red[r8 * 128 + tid];
        atomicAdd(&g_acc[gt * OO + obase + tid], s);
    }
}

// out[b,m] = fact_b * sum_h acc[b,m,h]*kinv[m,h]  -  sum_h relu(beq[m,h])*kinv[m,h]
__global__ void k_out(const float* __restrict__ kinv, const float* __restrict__ beq,
                      float* __restrict__ out) {
    int t = blockIdx.x * blockDim.x + threadIdx.x;
    if (t >= BB * MM) return;
    int b = t >> 6;
    int m = t & 63;
    float fb = g_factb[b];
    float s = 0.f, z = 0.f;
    #pragma unroll
    for (int h = 0; h < HH; h++) {
        float kv = kinv[m * HH + h];
        s += g_acc[b * OO + m * HH + h] * kv;
        z += fmaxf(beq[m * HH + h], 0.f) * kv;
    }
    out[t] = fb * s - z;
}

// ---------------- launch ------------------------------------------------------

extern "C" void kernel_launch(void* const* d_in, const int* in_sizes, int n_in,
                              void* d_out, int out_size) {
    const float* x    = (const float*)d_in[0];   // (N,16)
    const float* ea   = (const float*)d_in[1];   // (E,4)
    const float* keq  = (const float*)d_in[2];   // (M,5,H,FIN)
    const float* kinv = (const float*)d_in[3];   // (M,1,1,H)
    const float* beq  = (const float*)d_in[4];   // (1,M,1,H)
    // d_in[5] = bias_inv (cancels in psi - zerograph)
    const int* ei     = (const int*)d_in[6];     // (2,E)
    const int* batch  = (const int*)d_in[7];     // (N,)
    float* out = (float*)d_out;

    k_zero<<<512, 256>>>();
    k_count<<<(NN + 255) / 256, 256>>>(batch);
    k_prepw<<<(84 * OO + 255) / 256, 256>>>(keq);
    k_edge<<<(EE + 255) / 256, 256>>>(ei, ea);
    k_node<<<(NN + 255) / 256, 256>>>(x, ea, batch);
    k_gfin<<<(BB * FIN + 255) / 256, 256>>>();
    k_cg<<<(BB * OO) / 256, 256>>>(beq);
    dim3 gg((NN + 63) / 64, OO / 128);
    k_gemm<<<gg, 128>>>(batch);
    k_out<<<(BB * MM + 255) / 256, 256>>>(kinv, beq, out);
}